// round 10
// baseline (speedup 1.0000x reference)
#include <cuda_runtime.h>
#include <cuda_fp16.h>
#include <cstdint>

// ============================================================================
// MHMLP: out[b,h] = lrelu( sum_n lrelu( x[b,:]·W1[h,:,n] + b1[h,n] ) * W2[h,n] + b2[h] )
// B=2048, H=64, D=512(K), HID=2048(N). fp32 in/out.
// R10 = R8 chassis (256 thr, two independent n-halves, 64x64 warp tiles,
// W double buffer) + fp16-ACCUMULATE HMMA (rate experiment: rt4 vs rt8).
// fp16 accumulation confined to k=64 chains (4 chained HMMAs), promoted to
// fp32 accumulators once per iteration. Chains interleaved 8-wide to hide
// HMMA RAW latency. fb fragments for the whole iter held in registers.
// ============================================================================
#define BB   2048
#define HH   64
#define DD   512
#define HID  2048

__device__ __half  g_W16[(size_t)HH * DD * HID];    // [h][d][n] fp16
__device__ __half  g_X16[(size_t)BB * DD];          // [b][d]   fp16

__device__ __forceinline__ uint32_t smem_to_u32(const void* p) {
    uint32_t a;
    asm("{ .reg .u64 t; cvta.to.shared.u64 t, %1; cvt.u32.u64 %0, t; }" : "=r"(a) : "l"(p));
    return a;
}
__device__ __forceinline__ void cp_async_16(uint32_t dst, const void* src) {
    asm volatile("cp.async.cg.shared.global [%0], [%1], 16;" :: "r"(dst), "l"(src));
}
#define CP_COMMIT()   asm volatile("cp.async.commit_group;" ::: "memory")
#define CP_WAIT0()    asm volatile("cp.async.wait_group 0;" ::: "memory")

#define LDSM_X4(r0, r1, r2, r3, addr) \
    asm volatile("ldmatrix.sync.aligned.m8n8.x4.shared.b16 {%0,%1,%2,%3}, [%4];" \
        : "=r"(r0), "=r"(r1), "=r"(r2), "=r"(r3) : "r"(addr))
#define LDSM_X4_T(r0, r1, r2, r3, addr) \
    asm volatile("ldmatrix.sync.aligned.m8n8.x4.trans.shared.b16 {%0,%1,%2,%3}, [%4];" \
        : "=r"(r0), "=r"(r1), "=r"(r2), "=r"(r3) : "r"(addr))

// fp16-accumulate HMMA: D = A*B + C, D/C are 2 b32 regs (4 halves)
__device__ __forceinline__ void mma_f16_init(uint32_t* d, const uint32_t* a,
                                             const uint32_t* b) {
    asm volatile(
        "mma.sync.aligned.m16n8k16.row.col.f16.f16.f16.f16 "
        "{%0,%1}, {%2,%3,%4,%5}, {%6,%7}, {%8,%9};"
        : "=r"(d[0]), "=r"(d[1])
        : "r"(a[0]), "r"(a[1]), "r"(a[2]), "r"(a[3]), "r"(b[0]), "r"(b[1]),
          "r"(0u), "r"(0u));
}
__device__ __forceinline__ void mma_f16_acc(uint32_t* d, const uint32_t* a,
                                            const uint32_t* b) {
    asm volatile(
        "mma.sync.aligned.m16n8k16.row.col.f16.f16.f16.f16 "
        "{%0,%1}, {%2,%3,%4,%5}, {%6,%7}, {%0,%1};"
        : "+r"(d[0]), "+r"(d[1])
        : "r"(a[0]), "r"(a[1]), "r"(a[2]), "r"(a[3]), "r"(b[0]), "r"(b[1]));
}

__device__ __forceinline__ float lrelu(float v) {
    return fmaxf(v, 0.f) + 0.01f * fminf(v, 0.f);
}

// ============================================================================
// Merged pre-pass: x fp32->fp16 (blocks [0,512)), W1 fp32->fp16 ([512,33280))
// ============================================================================
__global__ void convert_all_kernel(const float* __restrict__ x,
                                   const float* __restrict__ W1) {
    const float* src;
    __half* dst;
    size_t g;
    if (blockIdx.x < 512) {
        g = (size_t)blockIdx.x * 256 + threadIdx.x;
        src = x;  dst = g_X16;
    } else {
        g = (size_t)(blockIdx.x - 512) * 256 + threadIdx.x;
        src = W1; dst = g_W16;
    }
    const float4* p = reinterpret_cast<const float4*>(src) + g * 2;
    float4 a = p[0], b = p[1];
    __half2 h0 = __floats2half2_rn(a.x, a.y), h1 = __floats2half2_rn(a.z, a.w);
    __half2 h2 = __floats2half2_rn(b.x, b.y), h3 = __floats2half2_rn(b.z, b.w);
    uint4 o;
    o.x = *reinterpret_cast<uint32_t*>(&h0);
    o.y = *reinterpret_cast<uint32_t*>(&h1);
    o.z = *reinterpret_cast<uint32_t*>(&h2);
    o.w = *reinterpret_cast<uint32_t*>(&h3);
    *reinterpret_cast<uint4*>(dst + g * 8) = o;
}

// ============================================================================
// Main fused kernel
// Grid: 1024 = 64 heads x 16 m-tiles. 256 threads = 8 warps.
// Warps 0-3 = half 0 (n-chunks 0-7), warps 4-7 = half 1 (n-chunks 8-15).
// Within a half: 2m x 2n warps, warp tile 64m x 64n.
// Per iter: fp16-acc HMMA chains over k=64 (4 HMMAs), 8 chains interleaved
// per mi block, promoted to fp32 acc after each mi block.
//
// SMEM:
//   [0..131072)        X: [kb][128m][64k halves], 128B rows, swizzled
//   [131072..196608)   W: 2 halves x 2 bufs x (64k x 128n), 256B rows, swizzled
//   [196608..212992)   bw: float2[2048] = (b1, W2)
//   [212992..215040)   part: float[128][4]
// ============================================================================
#define SM_X    0
#define SM_W    131072
#define SM_BW   196608
#define SM_PART 212992
#define SMEM_TOTAL 215040
#define NTHREADS 256

// fill chunk c (c in [0,64): nc_local=c>>3, kb=c&7) into buffer (c&1)
__device__ __forceinline__ void fill_w_chunk(const __half* __restrict__ Wh,
                                             uint32_t sb, int half, int c, int ht) {
    int nc = half * 8 + (c >> 3);
    int kb = c & 7;
    uint32_t base = sb + SM_W + half * 32768 + (c & 1) * 16384;
    const __half* src = Wh + (size_t)(kb * 64) * HID + nc * 128;
#pragma unroll
    for (int i = 0; i < 8; ++i) {
        int idx = i * 128 + ht;                 // 1024 chunks of 16B
        int kr = idx >> 4, j = idx & 15;
        uint32_t dst = base + kr * 256 + ((j * 16) ^ ((kr & 7) << 4));
        cp_async_16(dst, src + (size_t)kr * HID + j * 8);
    }
}

__global__ void __launch_bounds__(NTHREADS, 1) mhmlp_main(
    const float* __restrict__ b1g, const float* __restrict__ w2g,
    const float* __restrict__ b2g, float* __restrict__ out)
{
    extern __shared__ char smem[];
    uint32_t sb = smem_to_u32(smem);
    int tid  = threadIdx.x;
    int lane = tid & 31;
    int wid  = tid >> 5;
    int half = wid >> 2;        // 0 or 1
    int w4   = wid & 3;         // warp within half
    int wm   = w4 >> 1;         // 0..1 (64-row band)
    int wn   = w4 & 1;          // 0..1 (64-col half of the 128n chunk)
    int ht   = tid & 127;       // thread index within half
    int h  = blockIdx.x >> 4;
    int m0 = (blockIdx.x & 15) * 128;

    const __half* Wh = g_W16 + (size_t)h * DD * HID;

    // ---- X tile fill (all 256 threads): [kb][m][64k], swizzled 128B rows ----
#pragma unroll
    for (int i = 0; i < 32; ++i) {
        int idx = i * NTHREADS + tid;            // 8192 chunks of 16B
        int m = idx >> 6, j = idx & 63;
        int kb = j >> 3, jj = j & 7;
        uint32_t dst = sb + SM_X + kb * 16384 + m * 128 + ((jj * 16) ^ ((m & 7) << 4));
        cp_async_16(dst, g_X16 + (size_t)(m0 + m) * DD + kb * 64 + jj * 8);
    }
    fill_w_chunk(Wh, sb, half, 0, ht);
    CP_COMMIT();

    // ---- bias/W2 table into smem ----
    float2* bw = reinterpret_cast<float2*>(smem + SM_BW);
#pragma unroll
    for (int i = 0; i < 8; ++i) {
        int n = i * NTHREADS + tid;
        bw[n] = make_float2(b1g[h * HID + n], w2g[h * HID + n]);
    }
    CP_WAIT0();
    __syncthreads();            // X + both W0 chunks + bw visible

    float acc[4][8][4];
#pragma unroll
    for (int mi = 0; mi < 4; ++mi)
#pragma unroll
        for (int ni = 0; ni < 8; ++ni)
#pragma unroll
            for (int r = 0; r < 4; ++r) acc[mi][ni][r] = 0.f;
    float rowacc[8];
#pragma unroll
    for (int i = 0; i < 8; ++i) rowacc[i] = 0.f;

    int la = lane & 15;
    int lb = lane >> 4;
    int lmask = (lane & 7) << 4;
    int barid = 1 + half;

    uint32_t fb[4][4][4];       // [nb][ks][4] held for the whole iteration
    uint32_t fa[4][4];          // [ks][4] per mi block
    uint32_t c16[4][2][2];      // fp16 chain accumulators: [nb][j][2]

    for (int t = 0; t < 64; ++t) {
        // W(t) ready: committed at top of t-1 (or init for t=0)
        CP_WAIT0();
        asm volatile("bar.sync %0, %1;" :: "r"(barid), "r"(128) : "memory");
        if (t + 1 < 64) fill_w_chunk(Wh, sb, half, t + 1, ht);
        CP_COMMIT();

        int nc = half * 8 + (t >> 3);
        int kb = t & 7;
        uint32_t abase = sb + SM_X + kb * 16384;
        uint32_t bbase = sb + SM_W + half * 32768 + (t & 1) * 16384;

        // ---- load all W fragments for this iteration ----
#pragma unroll
        for (int nb = 0; nb < 4; ++nb)
#pragma unroll
            for (int ks = 0; ks < 4; ++ks) {
                int kr = ks * 16 + la;
                uint32_t bd = bbase + kr * 256 +
                              (((wn * 64 + nb * 16 + lb * 8) * 2) ^ lmask);
                LDSM_X4_T(fb[nb][ks][0], fb[nb][ks][1], fb[nb][ks][2], fb[nb][ks][3], bd);
            }

        // ---- per mi block: fp16 chains over k=64, then promote ----
#pragma unroll
        for (int mi = 0; mi < 4; ++mi) {
#pragma unroll
            for (int ks = 0; ks < 4; ++ks) {
                int m = wm * 64 + mi * 16 + la;
                uint32_t ad = abase + m * 128 + ((ks * 32 + lb * 16) ^ lmask);
                LDSM_X4(fa[ks][0], fa[ks][1], fa[ks][2], fa[ks][3], ad);
            }
            // 8 interleaved chains (nb x j); dependent HMMAs 8 issues apart
#pragma unroll
            for (int ks = 0; ks < 4; ++ks) {
#pragma unroll
                for (int nb = 0; nb < 4; ++nb)
#pragma unroll
                    for (int j = 0; j < 2; ++j) {
                        if (ks == 0) mma_f16_init(c16[nb][j], fa[0], &fb[nb][0][j * 2]);
                        else         mma_f16_acc (c16[nb][j], fa[ks], &fb[nb][ks][j * 2]);
                    }
            }
            // promote fp16 chunk sums into fp32 accumulators
#pragma unroll
            for (int nb = 0; nb < 4; ++nb)
#pragma unroll
                for (int j = 0; j < 2; ++j) {
                    int ni = nb * 2 + j;
                    float2 f0 = __half22float2(*reinterpret_cast<__half2*>(&c16[nb][j][0]));
                    float2 f1 = __half22float2(*reinterpret_cast<__half2*>(&c16[nb][j][1]));
                    acc[mi][ni][0] += f0.x;
                    acc[mi][ni][1] += f0.y;
                    acc[mi][ni][2] += f1.x;
                    acc[mi][ni][3] += f1.y;
                }
        }

        if (kb == 7) {
            // fold 128-col n-chunk: bias + leaky + dot(W2)
            int ncb = nc * 128 + wn * 64 + (lane & 3) * 2;
#pragma unroll
            for (int mi = 0; mi < 4; ++mi) {
#pragma unroll
                for (int ni = 0; ni < 8; ++ni) {
                    int n = ncb + ni * 8;
                    float2 p0 = bw[n];
                    float2 p1 = bw[n + 1];
                    rowacc[mi * 2 + 0] = fmaf(lrelu(acc[mi][ni][0] + p0.x), p0.y, rowacc[mi * 2 + 0]);
                    rowacc[mi * 2 + 0] = fmaf(lrelu(acc[mi][ni][1] + p1.x), p1.y, rowacc[mi * 2 + 0]);
                    rowacc[mi * 2 + 1] = fmaf(lrelu(acc[mi][ni][2] + p0.x), p0.y, rowacc[mi * 2 + 1]);
                    rowacc[mi * 2 + 1] = fmaf(lrelu(acc[mi][ni][3] + p1.x), p1.y, rowacc[mi * 2 + 1]);
                    acc[mi][ni][0] = 0.f; acc[mi][ni][1] = 0.f;
                    acc[mi][ni][2] = 0.f; acc[mi][ni][3] = 0.f;
                }
            }
        }
    }

    // ---- reduce rowacc across the 4 lanes sharing each row ----
#pragma unroll
    for (int i = 0; i < 8; ++i) {
        rowacc[i] += __shfl_xor_sync(0xffffffffu, rowacc[i], 1);
        rowacc[i] += __shfl_xor_sync(0xffffffffu, rowacc[i], 2);
    }
    float* part = reinterpret_cast<float*>(smem + SM_PART);
    if ((lane & 3) == 0) {
        int rq = lane >> 2;                   // 0..7
        int col = half * 2 + wn;
#pragma unroll
        for (int mi = 0; mi < 4; ++mi) {
            int rbase = wm * 64 + mi * 16;
            part[(rbase + 0 + rq) * 4 + col] = rowacc[mi * 2 + 0];
            part[(rbase + 8 + rq) * 4 + col] = rowacc[mi * 2 + 1];
        }
    }
    __syncthreads();
    if (tid < 128) {
        float s = part[tid * 4] + part[tid * 4 + 1] + part[tid * 4 + 2] +
                  part[tid * 4 + 3] + b2g[h];
        s = lrelu(s);
        out[(size_t)(m0 + tid) * HH + h] = s;
    }
}

// ============================================================================
// Launch
// ============================================================================
extern "C" void kernel_launch(void* const* d_in, const int* in_sizes, int n_in,
                              void* d_out, int out_size) {
    const float* x  = (const float*)d_in[0];
    const float* W1 = (const float*)d_in[1];
    const float* b1 = (const float*)d_in[2];
    const float* W2 = (const float*)d_in[3];
    const float* b2 = (const float*)d_in[4];
    float* out = (float*)d_out;

    convert_all_kernel<<<33280, 256>>>(x, W1);

    cudaFuncSetAttribute(mhmlp_main, cudaFuncAttributeMaxDynamicSharedMemorySize, SMEM_TOTAL);
    mhmlp_main<<<1024, NTHREADS, SMEM_TOTAL>>>(b1, W2, b2, out);
}